// round 8
// baseline (speedup 1.0000x reference)
#include <cuda_runtime.h>
#include <math.h>

#define PP 3
#define NN 50000
#define EE 256000
#define CC 5
#define FF 68
#define FE 16
#define FN 64
#define F2 (2*FF)   // 136

typedef unsigned long long ull;

#define PACK_F32X2(out, lo, hi) \
    asm("mov.b64 %0, {%1, %2};" : "=l"(out) : "f"(lo), "f"(hi))
#define UNPACK_F32X2(lo, hi, in) \
    asm("mov.b64 {%0, %1}, %2;" : "=f"(lo), "=f"(hi) : "l"(in))
#define FMA_F32X2(d, a, b, c) \
    asm("fma.rn.f32x2 %0, %1, %2, %3;" : "=l"(d) : "l"(a), "l"(b), "l"(c))

__device__ __forceinline__ float tanh_fast(float x) {
    float y; asm("tanh.approx.f32 %0, %1;" : "=f"(y) : "f"(x)); return y;
}

// Scratch: aggr [P,N,C,F] = 204 MB, A/B partials [P,N,C,16] = 48 MB each
__device__ __align__(16) float g_aggr[(size_t)PP*NN*CC*FF];
__device__ __align__(16) float g_A[(size_t)PP*NN*CC*FE];
__device__ __align__(16) float g_B[(size_t)PP*NN*CC*FE];
__device__ int g_is64;

__global__ void detect_kernel(const void* __restrict__ ei) {
    const long long* q = (const long long*)ei;
    int ok = 1;
    for (int i = 0; i < 64; ++i) {
        long long v = q[i];
        if (v < 0 || v >= NN) { ok = 0; break; }
    }
    g_is64 = ok;
}

__global__ void zero_kernel() {
    const size_t total = (size_t)PP*NN*CC*FF/4;
    float4* p = (float4*)g_aggr;
    const float4 z = make_float4(0.f, 0.f, 0.f, 0.f);
    for (size_t i = (size_t)blockIdx.x*blockDim.x + threadIdx.x; i < total;
         i += (size_t)gridDim.x*blockDim.x)
        p[i] = z;
}

__device__ __forceinline__ void red4(float* addr, float a, float b, float c, float d) {
    asm volatile("red.global.add.v4.f32 [%0], {%1,%2,%3,%4};"
                 :: "l"(addr), "f"(a), "f"(b), "f"(c), "f"(d) : "memory");
}

// 16 outputs (8 f32x2 acc) += u * w[0..15]
__device__ __forceinline__ void fma16(ull* acc2, const float* wk, float u) {
    ull uu; PACK_F32X2(uu, u, u);
    const ulonglong2* w = (const ulonglong2*)wk;
    #pragma unroll
    for (int j = 0; j < 4; ++j) {
        ulonglong2 wv = w[j];
        FMA_F32X2(acc2[2*j+0], uu, wv.x, acc2[2*j+0]);
        FMA_F32X2(acc2[2*j+1], uu, wv.y, acc2[2*j+1]);
    }
}

// ---------------------------------------------------------------------------
// Precompute kernel: per (node, class), A = W1a.x + b1 and B = W1b.x.
// ---------------------------------------------------------------------------
__global__ __launch_bounds__(256) void pre_kernel(
    const float* __restrict__ x,
    const float* __restrict__ We1, const float* __restrict__ be1)
{
    __shared__ __align__(16) float sW[CC*FF*32];  // 43.5 KB
    __shared__ float sb1[CC*FE];

    const int p = blockIdx.y;
    for (int i = threadIdx.x; i < CC*FF*32; i += blockDim.x) {
        const int c = i / (FF*32);
        const int r = i % (FF*32);
        const int k = r / 32;
        const int j = r % 32;
        const int g = (j < 16) ? j : j - 16;
        const int kk = (j < 16) ? k : FF + k;
        sW[i] = We1[(((size_t)p*CC + c)*FE + g)*F2 + kk];
    }
    for (int i = threadIdx.x; i < CC*FE; i += blockDim.x)
        sb1[i] = be1[p*CC*FE + i];
    __syncthreads();

    const int idx = blockIdx.x*blockDim.x + threadIdx.x;
    if (idx >= NN*CC) return;
    const int n = idx / CC;
    const int c = idx % CC;

    const float4* x4 = (const float4*)(x + (((size_t)p*NN + n)*CC + c)*FF);

    ull accA[8], accB[8];
    #pragma unroll
    for (int j = 0; j < 8; ++j) {
        PACK_F32X2(accA[j], sb1[c*FE + 2*j], sb1[c*FE + 2*j + 1]);
        float z = 0.f;
        PACK_F32X2(accB[j], z, z);
    }

    const float* wb = sW + c*FF*32;
    #pragma unroll 1
    for (int fc = 0; fc < FF/4; ++fc) {
        const float4 u = x4[fc];
        const float* wk = wb + (4*fc)*32;
        fma16(accA, wk + 0*32,      u.x); fma16(accB, wk + 0*32 + 16, u.x);
        fma16(accA, wk + 1*32,      u.y); fma16(accB, wk + 1*32 + 16, u.y);
        fma16(accA, wk + 2*32,      u.z); fma16(accB, wk + 2*32 + 16, u.z);
        fma16(accA, wk + 3*32,      u.w); fma16(accB, wk + 3*32 + 16, u.w);
    }

    float* Ao = g_A + (((size_t)p*NN + n)*CC + c)*FE;
    float* Bo = g_B + (((size_t)p*NN + n)*CC + c)*FE;
    #pragma unroll
    for (int j = 0; j < 8; j += 2) {
        float a0, a1, a2, a3, b0, b1, b2, b3;
        UNPACK_F32X2(a0, a1, accA[j]);
        UNPACK_F32X2(a2, a3, accA[j+1]);
        UNPACK_F32X2(b0, b1, accB[j]);
        UNPACK_F32X2(b2, b3, accB[j+1]);
        *(float4*)(Ao + 2*j) = make_float4(a0, a1, a2, a3);
        *(float4*)(Bo + 2*j) = make_float4(b0, b1, b2, b3);
    }
}

// ---------------------------------------------------------------------------
// Edge kernel: gather A[dst]+B[src], tanh-gate, class softmax, scatter w*x_j.
// ---------------------------------------------------------------------------
__global__ __launch_bounds__(256) void edge_kernel(
    const float* __restrict__ x, const void* __restrict__ ei,
    const float* __restrict__ We2, const float* __restrict__ be2)
{
    __shared__ float sW2[CC*FE];
    __shared__ float sb2[CC];

    const int p = blockIdx.y;
    for (int i = threadIdx.x; i < CC*FE; i += blockDim.x)
        sW2[i] = We2[p*CC*FE + i];
    if (threadIdx.x < CC) sb2[threadIdx.x] = be2[p*CC + threadIdx.x];
    __syncthreads();

    const int is64 = g_is64;
    const long long* ei64 = (const long long*)ei;
    const int*       ei32 = (const int*)ei;
    const size_t base = (size_t)p*2*EE;

    const int e = blockIdx.x*blockDim.x + threadIdx.x;   // EE % 256 == 0
    int s, d;
    if (is64) {
        s = (int)ei64[base + e];
        d = (int)ei64[base + EE + e];
    } else {
        s = ei32[base + e];
        d = ei32[base + EE + e];
    }

    const float4* Ad = (const float4*)(g_A + ((size_t)p*NN + d)*(CC*FE));
    const float4* Bs = (const float4*)(g_B + ((size_t)p*NN + s)*(CC*FE));

    float lg[CC];
    #pragma unroll
    for (int c = 0; c < CC; ++c) {
        float l = sb2[c];
        #pragma unroll
        for (int j = 0; j < 4; ++j) {
            const float4 a = Ad[c*4 + j];
            const float4 b = Bs[c*4 + j];
            l += tanh_fast(a.x + b.x) * sW2[c*FE + 4*j + 0]
               + tanh_fast(a.y + b.y) * sW2[c*FE + 4*j + 1]
               + tanh_fast(a.z + b.z) * sW2[c*FE + 4*j + 2]
               + tanh_fast(a.w + b.w) * sW2[c*FE + 4*j + 3];
        }
        lg[c] = l;
    }

    float mx = lg[0];
    #pragma unroll
    for (int c = 1; c < CC; ++c) mx = fmaxf(mx, lg[c]);
    float w[CC];
    float sum = 0.f;
    #pragma unroll
    for (int c = 0; c < CC; ++c) { w[c] = expf(lg[c] - mx); sum += w[c]; }
    const float inv = 1.f / sum;

    const float* xj = x + ((size_t)p*NN + s)*(CC*FF);
    float* ap = g_aggr + ((size_t)p*NN + d)*(CC*FF);
    #pragma unroll
    for (int c = 0; c < CC; ++c) {
        const float wc = w[c] * inv;
        const float4* mj = (const float4*)(xj + c*FF);
        float* a = ap + c*FF;
        #pragma unroll 1
        for (int fc = 0; fc < FF/4; ++fc) {
            const float4 v = mj[fc];
            red4(a + 4*fc, wc*v.x, wc*v.y, wc*v.z, wc*v.w);
        }
    }
}

// ---------------------------------------------------------------------------
// Node kernel v4: spill-free register tiling.
// Block = 512 threads = 256 nodes of one (plane, class).
// Thread = 2 nodes (ln, ln+128) x 16 outputs (g-quarter gq = tid&3).
// Per k: 4 LDS.128 weights feed 16 FFMA2 (1:4); per-thread regs ~75.
// Hidden h staged via smem [256][68] (stride 68: float4-aligned stores,
// conflict-free scalar reads).
// ---------------------------------------------------------------------------
#define NPB 256
#define HS  68

__global__ __launch_bounds__(512) void node_kernel(
    const float* __restrict__ x,
    const float* __restrict__ Wn1, const float* __restrict__ bn1,
    const float* __restrict__ Wn2, const float* __restrict__ bn2,
    float* __restrict__ out)
{
    extern __shared__ __align__(16) float sm[];
    float* sW1t = sm;                    // [136][64]
    float* sW2t = sW1t + F2*FN;          // [64][64]
    float* sb1  = sW2t + FN*FN;          // 64
    float* sb2  = sb1 + FN;              // 64
    float* hs   = sb2 + FN;              // [256][68]

    const int c = blockIdx.y;
    const int p = blockIdx.z;
    const size_t wo = (size_t)p*CC + c;
    for (int i = threadIdx.x; i < F2*FN; i += blockDim.x) {
        const int k = i >> 6, g = i & 63;
        sW1t[i] = Wn1[(wo*FN + g)*F2 + k];
    }
    for (int i = threadIdx.x; i < FN*FN; i += blockDim.x) {
        const int k = i >> 6, g = i & 63;
        sW2t[i] = Wn2[(wo*FN + g)*FN + k];
    }
    if (threadIdx.x < FN) {
        sb1[threadIdx.x] = bn1[wo*FN + threadIdx.x];
        sb2[threadIdx.x] = bn2[wo*FN + threadIdx.x];
    }
    __syncthreads();

    const int gq  = threadIdx.x & 3;
    const int nl  = threadIdx.x >> 2;        // 0..127
    const int ln0 = nl;
    const int ln1 = nl + 128;
    const int n0  = blockIdx.x*NPB + ln0;
    const int n1  = blockIdx.x*NPB + ln1;
    const int m0  = min(n0, NN - 1);
    const int m1  = min(n1, NN - 1);

    const float4* x40 = (const float4*)(x      + (((size_t)p*NN + m0)*CC + c)*FF);
    const float4* x41 = (const float4*)(x      + (((size_t)p*NN + m1)*CC + c)*FF);
    const float4* a40 = (const float4*)(g_aggr + (((size_t)p*NN + m0)*CC + c)*FF);
    const float4* a41 = (const float4*)(g_aggr + (((size_t)p*NN + m1)*CC + c)*FF);

    ull acc0[8], acc1[8];
    #pragma unroll
    for (int j = 0; j < 8; ++j) {
        ull b; PACK_F32X2(b, sb1[gq*16 + 2*j], sb1[gq*16 + 2*j + 1]);
        acc0[j] = b; acc1[j] = b;
    }

#define K_STEP2(S0, S1, WPTR)                                             \
    do {                                                                  \
        const ulonglong2* wq = (const ulonglong2*)(WPTR);                 \
        ulonglong2 w0 = wq[0], w1 = wq[1], w2 = wq[2], w3 = wq[3];        \
        ull uu;                                                           \
        PACK_F32X2(uu, S0, S0);                                           \
        FMA_F32X2(acc0[0], uu, w0.x, acc0[0]);                            \
        FMA_F32X2(acc0[1], uu, w0.y, acc0[1]);                            \
        FMA_F32X2(acc0[2], uu, w1.x, acc0[2]);                            \
        FMA_F32X2(acc0[3], uu, w1.y, acc0[3]);                            \
        FMA_F32X2(acc0[4], uu, w2.x, acc0[4]);                            \
        FMA_F32X2(acc0[5], uu, w2.y, acc0[5]);                            \
        FMA_F32X2(acc0[6], uu, w3.x, acc0[6]);                            \
        FMA_F32X2(acc0[7], uu, w3.y, acc0[7]);                            \
        PACK_F32X2(uu, S1, S1);                                           \
        FMA_F32X2(acc1[0], uu, w0.x, acc1[0]);                            \
        FMA_F32X2(acc1[1], uu, w0.y, acc1[1]);                            \
        FMA_F32X2(acc1[2], uu, w1.x, acc1[2]);                            \
        FMA_F32X2(acc1[3], uu, w1.y, acc1[3]);                            \
        FMA_F32X2(acc1[4], uu, w2.x, acc1[4]);                            \
        FMA_F32X2(acc1[5], uu, w2.y, acc1[5]);                            \
        FMA_F32X2(acc1[6], uu, w3.x, acc1[6]);                            \
        FMA_F32X2(acc1[7], uu, w3.y, acc1[7]);                            \
    } while (0)

    // ---- layer 1: x segment ----
    #pragma unroll 1
    for (int fc = 0; fc < FF/4; ++fc) {
        const float4 u0 = x40[fc], u1 = x41[fc];
        const float* wk = sW1t + (4*fc)*FN + gq*16;
        K_STEP2(u0.x, u1.x, wk + 0*FN);
        K_STEP2(u0.y, u1.y, wk + 1*FN);
        K_STEP2(u0.z, u1.z, wk + 2*FN);
        K_STEP2(u0.w, u1.w, wk + 3*FN);
    }
    // ---- layer 1: aggr segment ----
    #pragma unroll 1
    for (int fc = 0; fc < FF/4; ++fc) {
        const float4 u0 = a40[fc], u1 = a41[fc];
        const float* wk = sW1t + (FF + 4*fc)*FN + gq*16;
        K_STEP2(u0.x, u1.x, wk + 0*FN);
        K_STEP2(u0.y, u1.y, wk + 1*FN);
        K_STEP2(u0.z, u1.z, wk + 2*FN);
        K_STEP2(u0.w, u1.w, wk + 3*FN);
    }

    // ---- h -> smem (tanh approx on hidden) ----
    {
        float* h0 = hs + ln0*HS + gq*16;
        float* h1 = hs + ln1*HS + gq*16;
        #pragma unroll
        for (int q = 0; q < 8; q += 2) {
            float a0, a1, b0, b1;
            UNPACK_F32X2(a0, a1, acc0[q]);
            UNPACK_F32X2(b0, b1, acc0[q+1]);
            *(float4*)(h0 + 2*q) = make_float4(tanh_fast(a0), tanh_fast(a1),
                                               tanh_fast(b0), tanh_fast(b1));
            UNPACK_F32X2(a0, a1, acc1[q]);
            UNPACK_F32X2(b0, b1, acc1[q+1]);
            *(float4*)(h1 + 2*q) = make_float4(tanh_fast(a0), tanh_fast(a1),
                                               tanh_fast(b0), tanh_fast(b1));
        }
    }
    __syncthreads();

    // ---- layer 2 ----
    #pragma unroll
    for (int j = 0; j < 8; ++j) {
        ull b; PACK_F32X2(b, sb2[gq*16 + 2*j], sb2[gq*16 + 2*j + 1]);
        acc0[j] = b; acc1[j] = b;
    }

    const float* h0 = hs + ln0*HS;
    const float* h1 = hs + ln1*HS;
    #pragma unroll 4
    for (int k = 0; k < FN; ++k) {
        const float* wk = sW2t + k*FN + gq*16;
        K_STEP2(h0[k], h1[k], wk);
    }

    // ---- output (accurate tanh) ----
    if (n0 < NN) {
        float* op = out + (((size_t)p*NN + n0)*CC + c)*FN + gq*16;
        #pragma unroll
        for (int q = 0; q < 8; q += 2) {
            float a0, a1, b0, b1;
            UNPACK_F32X2(a0, a1, acc0[q]);
            UNPACK_F32X2(b0, b1, acc0[q+1]);
            *(float4*)(op + 2*q) =
                make_float4(tanhf(a0), tanhf(a1), tanhf(b0), tanhf(b1));
        }
    }
    if (n1 < NN) {
        float* op = out + (((size_t)p*NN + n1)*CC + c)*FN + gq*16;
        #pragma unroll
        for (int q = 0; q < 8; q += 2) {
            float a0, a1, b0, b1;
            UNPACK_F32X2(a0, a1, acc1[q]);
            UNPACK_F32X2(b0, b1, acc1[q+1]);
            *(float4*)(op + 2*q) =
                make_float4(tanhf(a0), tanhf(a1), tanhf(b0), tanhf(b1));
        }
    }
#undef K_STEP2
}

extern "C" void kernel_launch(void* const* d_in, const int* in_sizes, int n_in,
                              void* d_out, int out_size) {
    const float* x   = (const float*)d_in[0];
    const void*  ei  = d_in[1];
    const float* We1 = (const float*)d_in[2];
    const float* be1 = (const float*)d_in[3];
    const float* We2 = (const float*)d_in[4];
    const float* be2 = (const float*)d_in[5];
    const float* Wn1 = (const float*)d_in[6];
    const float* bn1 = (const float*)d_in[7];
    const float* Wn2 = (const float*)d_in[8];
    const float* bn2 = (const float*)d_in[9];
    float* out = (float*)d_out;

    const int smem_node =
        (F2*FN + FN*FN + 2*FN + NPB*HS) * (int)sizeof(float);  // ~121 KB
    cudaFuncSetAttribute(node_kernel,
                         cudaFuncAttributeMaxDynamicSharedMemorySize, smem_node);

    detect_kernel<<<1, 1>>>(ei);
    zero_kernel<<<1024, 256>>>();

    dim3 gp((NN*CC + 255)/256, PP);
    pre_kernel<<<gp, 256>>>(x, We1, be1);

    dim3 ge(EE/256, PP);
    edge_kernel<<<ge, 256>>>(x, ei, We2, be2);

    dim3 gn((NN + NPB - 1)/NPB, CC, PP);
    node_kernel<<<gn, 512, smem_node>>>(x, Wn1, bn1, Wn2, bn2, out);
}

// round 9
// speedup vs baseline: 1.2010x; 1.2010x over previous
#include <cuda_runtime.h>
#include <math.h>

#define PP 3
#define NN 50000
#define EE 256000
#define CC 5
#define FF 68
#define FE 16
#define FN 64
#define F2 (2*FF)   // 136

typedef unsigned long long ull;

#define PACK_F32X2(out, lo, hi) \
    asm("mov.b64 %0, {%1, %2};" : "=l"(out) : "f"(lo), "f"(hi))
#define UNPACK_F32X2(lo, hi, in) \
    asm("mov.b64 {%0, %1}, %2;" : "=f"(lo), "=f"(hi) : "l"(in))
#define FMA_F32X2(d, a, b, c) \
    asm("fma.rn.f32x2 %0, %1, %2, %3;" : "=l"(d) : "l"(a), "l"(b), "l"(c))

__device__ __forceinline__ float tanh_fast(float x) {
    float y; asm("tanh.approx.f32 %0, %1;" : "=f"(y) : "f"(x)); return y;
}

// Scratch: aggr 204 MB, A/B partials 48 MB each, hidden h 192 MB
__device__ __align__(16) float g_aggr[(size_t)PP*NN*CC*FF];
__device__ __align__(16) float g_A[(size_t)PP*NN*CC*FE];
__device__ __align__(16) float g_B[(size_t)PP*NN*CC*FE];
__device__ __align__(16) float g_h[(size_t)PP*NN*CC*FN];
__device__ int g_is64;

__global__ void detect_kernel(const void* __restrict__ ei) {
    const long long* q = (const long long*)ei;
    int ok = 1;
    for (int i = 0; i < 64; ++i) {
        long long v = q[i];
        if (v < 0 || v >= NN) { ok = 0; break; }
    }
    g_is64 = ok;
}

__global__ void zero_kernel() {
    const size_t total = (size_t)PP*NN*CC*FF/4;
    float4* p = (float4*)g_aggr;
    const float4 z = make_float4(0.f, 0.f, 0.f, 0.f);
    for (size_t i = (size_t)blockIdx.x*blockDim.x + threadIdx.x; i < total;
         i += (size_t)gridDim.x*blockDim.x)
        p[i] = z;
}

__device__ __forceinline__ void red4(float* addr, float a, float b, float c, float d) {
    asm volatile("red.global.add.v4.f32 [%0], {%1,%2,%3,%4};"
                 :: "l"(addr), "f"(a), "f"(b), "f"(c), "f"(d) : "memory");
}

// 16 outputs (8 f32x2 acc) += u * w[0..15]
__device__ __forceinline__ void fma16(ull* acc2, const float* wk, float u) {
    ull uu; PACK_F32X2(uu, u, u);
    const ulonglong2* w = (const ulonglong2*)wk;
    #pragma unroll
    for (int j = 0; j < 4; ++j) {
        ulonglong2 wv = w[j];
        FMA_F32X2(acc2[2*j+0], uu, wv.x, acc2[2*j+0]);
        FMA_F32X2(acc2[2*j+1], uu, wv.y, acc2[2*j+1]);
    }
}

// dual-node 16-FFMA2 step over 32 outputs (16 f32x2 accs per node)
#define K_STEP32(A0, A1, S0, S1, WPTR)                                    \
    do {                                                                  \
        const ulonglong2* wq = (const ulonglong2*)(WPTR);                 \
        ulonglong2 w0 = wq[0], w1 = wq[1], w2 = wq[2], w3 = wq[3];        \
        ulonglong2 w4 = wq[4], w5 = wq[5], w6 = wq[6], w7 = wq[7];        \
        ull uu;                                                           \
        PACK_F32X2(uu, S0, S0);                                           \
        FMA_F32X2(A0[0],  uu, w0.x, A0[0]);                               \
        FMA_F32X2(A0[1],  uu, w0.y, A0[1]);                               \
        FMA_F32X2(A0[2],  uu, w1.x, A0[2]);                               \
        FMA_F32X2(A0[3],  uu, w1.y, A0[3]);                               \
        FMA_F32X2(A0[4],  uu, w2.x, A0[4]);                               \
        FMA_F32X2(A0[5],  uu, w2.y, A0[5]);                               \
        FMA_F32X2(A0[6],  uu, w3.x, A0[6]);                               \
        FMA_F32X2(A0[7],  uu, w3.y, A0[7]);                               \
        FMA_F32X2(A0[8],  uu, w4.x, A0[8]);                               \
        FMA_F32X2(A0[9],  uu, w4.y, A0[9]);                               \
        FMA_F32X2(A0[10], uu, w5.x, A0[10]);                              \
        FMA_F32X2(A0[11], uu, w5.y, A0[11]);                              \
        FMA_F32X2(A0[12], uu, w6.x, A0[12]);                              \
        FMA_F32X2(A0[13], uu, w6.y, A0[13]);                              \
        FMA_F32X2(A0[14], uu, w7.x, A0[14]);                              \
        FMA_F32X2(A0[15], uu, w7.y, A0[15]);                              \
        PACK_F32X2(uu, S1, S1);                                           \
        FMA_F32X2(A1[0],  uu, w0.x, A1[0]);                               \
        FMA_F32X2(A1[1],  uu, w0.y, A1[1]);                               \
        FMA_F32X2(A1[2],  uu, w1.x, A1[2]);                               \
        FMA_F32X2(A1[3],  uu, w1.y, A1[3]);                               \
        FMA_F32X2(A1[4],  uu, w2.x, A1[4]);                               \
        FMA_F32X2(A1[5],  uu, w2.y, A1[5]);                               \
        FMA_F32X2(A1[6],  uu, w3.x, A1[6]);                               \
        FMA_F32X2(A1[7],  uu, w3.y, A1[7]);                               \
        FMA_F32X2(A1[8],  uu, w4.x, A1[8]);                               \
        FMA_F32X2(A1[9],  uu, w4.y, A1[9]);                               \
        FMA_F32X2(A1[10], uu, w5.x, A1[10]);                              \
        FMA_F32X2(A1[11], uu, w5.y, A1[11]);                              \
        FMA_F32X2(A1[12], uu, w6.x, A1[12]);                              \
        FMA_F32X2(A1[13], uu, w6.y, A1[13]);                              \
        FMA_F32X2(A1[14], uu, w7.x, A1[14]);                              \
        FMA_F32X2(A1[15], uu, w7.y, A1[15]);                              \
    } while (0)

// ---------------------------------------------------------------------------
// Precompute kernel: per (node, class), A = W1a.x + b1 and B = W1b.x.
// ---------------------------------------------------------------------------
__global__ __launch_bounds__(256) void pre_kernel(
    const float* __restrict__ x,
    const float* __restrict__ We1, const float* __restrict__ be1)
{
    __shared__ __align__(16) float sW[CC*FF*32];  // 43.5 KB
    __shared__ float sb1[CC*FE];

    const int p = blockIdx.y;
    for (int i = threadIdx.x; i < CC*FF*32; i += blockDim.x) {
        const int c = i / (FF*32);
        const int r = i % (FF*32);
        const int k = r / 32;
        const int j = r % 32;
        const int g = (j < 16) ? j : j - 16;
        const int kk = (j < 16) ? k : FF + k;
        sW[i] = We1[(((size_t)p*CC + c)*FE + g)*F2 + kk];
    }
    for (int i = threadIdx.x; i < CC*FE; i += blockDim.x)
        sb1[i] = be1[p*CC*FE + i];
    __syncthreads();

    const int idx = blockIdx.x*blockDim.x + threadIdx.x;
    if (idx >= NN*CC) return;
    const int n = idx / CC;
    const int c = idx % CC;

    const float4* x4 = (const float4*)(x + (((size_t)p*NN + n)*CC + c)*FF);

    ull accA[8], accB[8];
    #pragma unroll
    for (int j = 0; j < 8; ++j) {
        PACK_F32X2(accA[j], sb1[c*FE + 2*j], sb1[c*FE + 2*j + 1]);
        float z = 0.f;
        PACK_F32X2(accB[j], z, z);
    }

    const float* wb = sW + c*FF*32;
    #pragma unroll 1
    for (int fc = 0; fc < FF/4; ++fc) {
        const float4 u = x4[fc];
        const float* wk = wb + (4*fc)*32;
        fma16(accA, wk + 0*32,      u.x); fma16(accB, wk + 0*32 + 16, u.x);
        fma16(accA, wk + 1*32,      u.y); fma16(accB, wk + 1*32 + 16, u.y);
        fma16(accA, wk + 2*32,      u.z); fma16(accB, wk + 2*32 + 16, u.z);
        fma16(accA, wk + 3*32,      u.w); fma16(accB, wk + 3*32 + 16, u.w);
    }

    float* Ao = g_A + (((size_t)p*NN + n)*CC + c)*FE;
    float* Bo = g_B + (((size_t)p*NN + n)*CC + c)*FE;
    #pragma unroll
    for (int j = 0; j < 8; j += 2) {
        float a0, a1, a2, a3, b0, b1, b2, b3;
        UNPACK_F32X2(a0, a1, accA[j]);
        UNPACK_F32X2(a2, a3, accA[j+1]);
        UNPACK_F32X2(b0, b1, accB[j]);
        UNPACK_F32X2(b2, b3, accB[j+1]);
        *(float4*)(Ao + 2*j) = make_float4(a0, a1, a2, a3);
        *(float4*)(Bo + 2*j) = make_float4(b0, b1, b2, b3);
    }
}

// ---------------------------------------------------------------------------
// Edge kernel: gather A[dst]+B[src], tanh-gate, class softmax, scatter w*x_j.
// ---------------------------------------------------------------------------
__global__ __launch_bounds__(256) void edge_kernel(
    const float* __restrict__ x, const void* __restrict__ ei,
    const float* __restrict__ We2, const float* __restrict__ be2)
{
    __shared__ float sW2[CC*FE];
    __shared__ float sb2[CC];

    const int p = blockIdx.y;
    for (int i = threadIdx.x; i < CC*FE; i += blockDim.x)
        sW2[i] = We2[p*CC*FE + i];
    if (threadIdx.x < CC) sb2[threadIdx.x] = be2[p*CC + threadIdx.x];
    __syncthreads();

    const int is64 = g_is64;
    const long long* ei64 = (const long long*)ei;
    const int*       ei32 = (const int*)ei;
    const size_t base = (size_t)p*2*EE;

    const int e = blockIdx.x*blockDim.x + threadIdx.x;   // EE % 256 == 0
    int s, d;
    if (is64) {
        s = (int)ei64[base + e];
        d = (int)ei64[base + EE + e];
    } else {
        s = ei32[base + e];
        d = ei32[base + EE + e];
    }

    const float4* Ad = (const float4*)(g_A + ((size_t)p*NN + d)*(CC*FE));
    const float4* Bs = (const float4*)(g_B + ((size_t)p*NN + s)*(CC*FE));

    float lg[CC];
    #pragma unroll
    for (int c = 0; c < CC; ++c) {
        float l = sb2[c];
        #pragma unroll
        for (int j = 0; j < 4; ++j) {
            const float4 a = Ad[c*4 + j];
            const float4 b = Bs[c*4 + j];
            l += tanh_fast(a.x + b.x) * sW2[c*FE + 4*j + 0]
               + tanh_fast(a.y + b.y) * sW2[c*FE + 4*j + 1]
               + tanh_fast(a.z + b.z) * sW2[c*FE + 4*j + 2]
               + tanh_fast(a.w + b.w) * sW2[c*FE + 4*j + 3];
        }
        lg[c] = l;
    }

    float mx = lg[0];
    #pragma unroll
    for (int c = 1; c < CC; ++c) mx = fmaxf(mx, lg[c]);
    float w[CC];
    float sum = 0.f;
    #pragma unroll
    for (int c = 0; c < CC; ++c) { w[c] = expf(lg[c] - mx); sum += w[c]; }
    const float inv = 1.f / sum;

    const float* xj = x + ((size_t)p*NN + s)*(CC*FF);
    float* ap = g_aggr + ((size_t)p*NN + d)*(CC*FF);
    #pragma unroll
    for (int c = 0; c < CC; ++c) {
        const float wc = w[c] * inv;
        const float4* mj = (const float4*)(xj + c*FF);
        float* a = ap + c*FF;
        #pragma unroll 1
        for (int fc = 0; fc < FF/4; ++fc) {
            const float4 v = mj[fc];
            red4(a + 4*fc, wc*v.x, wc*v.y, wc*v.z, wc*v.w);
        }
    }
}

// ---------------------------------------------------------------------------
// node1: layer 1 (136 -> 64, tanh) into g_h. Small smem (35 KB), no sync
// after staging, 2-3 blocks/SM. Thread = 2 nodes x 32 outputs (gh = tid&1).
// Per k: 8 LDS.128 weights feed 32 FFMA2 (1:4).
// ---------------------------------------------------------------------------
__global__ __launch_bounds__(256, 2) void node1_kernel(
    const float* __restrict__ x,
    const float* __restrict__ Wn1, const float* __restrict__ bn1)
{
    __shared__ __align__(16) float sW1t[F2*FN];   // [k=136][g=64] 34.8 KB
    __shared__ float sb1[FN];

    const int c = blockIdx.y;
    const int p = blockIdx.z;
    const size_t wo = (size_t)p*CC + c;
    for (int i = threadIdx.x; i < F2*FN; i += blockDim.x) {
        const int k = i >> 6, g = i & 63;
        sW1t[i] = Wn1[(wo*FN + g)*F2 + k];
    }
    if (threadIdx.x < FN) sb1[threadIdx.x] = bn1[wo*FN + threadIdx.x];
    __syncthreads();

    const int gh  = threadIdx.x & 1;          // output half
    const int nl  = threadIdx.x >> 1;         // 0..127
    const int n0  = blockIdx.x*256 + nl;
    const int n1  = n0 + 128;
    const int m0  = min(n0, NN - 1);
    const int m1  = min(n1, NN - 1);

    const float4* x40 = (const float4*)(x      + (((size_t)p*NN + m0)*CC + c)*FF);
    const float4* x41 = (const float4*)(x      + (((size_t)p*NN + m1)*CC + c)*FF);
    const float4* a40 = (const float4*)(g_aggr + (((size_t)p*NN + m0)*CC + c)*FF);
    const float4* a41 = (const float4*)(g_aggr + (((size_t)p*NN + m1)*CC + c)*FF);

    ull acc0[16], acc1[16];
    #pragma unroll
    for (int j = 0; j < 16; ++j) {
        ull b; PACK_F32X2(b, sb1[gh*32 + 2*j], sb1[gh*32 + 2*j + 1]);
        acc0[j] = b; acc1[j] = b;
    }

    #pragma unroll 1
    for (int fc = 0; fc < FF/4; ++fc) {
        const float4 u0 = x40[fc], u1 = x41[fc];
        const float* wk = sW1t + (4*fc)*FN + gh*32;
        K_STEP32(acc0, acc1, u0.x, u1.x, wk + 0*FN);
        K_STEP32(acc0, acc1, u0.y, u1.y, wk + 1*FN);
        K_STEP32(acc0, acc1, u0.z, u1.z, wk + 2*FN);
        K_STEP32(acc0, acc1, u0.w, u1.w, wk + 3*FN);
    }
    #pragma unroll 1
    for (int fc = 0; fc < FF/4; ++fc) {
        const float4 u0 = a40[fc], u1 = a41[fc];
        const float* wk = sW1t + (FF + 4*fc)*FN + gh*32;
        K_STEP32(acc0, acc1, u0.x, u1.x, wk + 0*FN);
        K_STEP32(acc0, acc1, u0.y, u1.y, wk + 1*FN);
        K_STEP32(acc0, acc1, u0.z, u1.z, wk + 2*FN);
        K_STEP32(acc0, acc1, u0.w, u1.w, wk + 3*FN);
    }

    if (n0 < NN) {
        float* hp = g_h + (((size_t)p*NN + n0)*CC + c)*FN + gh*32;
        #pragma unroll
        for (int q = 0; q < 16; q += 2) {
            float a0, a1, b0, b1;
            UNPACK_F32X2(a0, a1, acc0[q]);
            UNPACK_F32X2(b0, b1, acc0[q+1]);
            *(float4*)(hp + 2*q) = make_float4(tanh_fast(a0), tanh_fast(a1),
                                               tanh_fast(b0), tanh_fast(b1));
        }
    }
    if (n1 < NN) {
        float* hp = g_h + (((size_t)p*NN + n1)*CC + c)*FN + gh*32;
        #pragma unroll
        for (int q = 0; q < 16; q += 2) {
            float a0, a1, b0, b1;
            UNPACK_F32X2(a0, a1, acc1[q]);
            UNPACK_F32X2(b0, b1, acc1[q+1]);
            *(float4*)(hp + 2*q) = make_float4(tanh_fast(a0), tanh_fast(a1),
                                               tanh_fast(b0), tanh_fast(b1));
        }
    }
}

// ---------------------------------------------------------------------------
// node2: layer 2 (64 -> 64, tanh) from g_h to out. smem = W2 only (16 KB).
// Same 2-node x 32-output thread tiling.
// ---------------------------------------------------------------------------
__global__ __launch_bounds__(256, 2) void node2_kernel(
    const float* __restrict__ Wn2, const float* __restrict__ bn2,
    float* __restrict__ out)
{
    __shared__ __align__(16) float sW2t[FN*FN];   // [k=64][g=64] 16 KB
    __shared__ float sb2[FN];

    const int c = blockIdx.y;
    const int p = blockIdx.z;
    const size_t wo = (size_t)p*CC + c;
    for (int i = threadIdx.x; i < FN*FN; i += blockDim.x) {
        const int k = i >> 6, g = i & 63;
        sW2t[i] = Wn2[(wo*FN + g)*FN + k];
    }
    if (threadIdx.x < FN) sb2[threadIdx.x] = bn2[wo*FN + threadIdx.x];
    __syncthreads();

    const int gh  = threadIdx.x & 1;
    const int nl  = threadIdx.x >> 1;
    const int n0  = blockIdx.x*256 + nl;
    const int n1  = n0 + 128;
    const int m0  = min(n0, NN - 1);
    const int m1  = min(n1, NN - 1);

    const float4* h40 = (const float4*)(g_h + (((size_t)p*NN + m0)*CC + c)*FN);
    const float4* h41 = (const float4*)(g_h + (((size_t)p*NN + m1)*CC + c)*FN);

    ull acc0[16], acc1[16];
    #pragma unroll
    for (int j = 0; j < 16; ++j) {
        ull b; PACK_F32X2(b, sb2[gh*32 + 2*j], sb2[gh*32 + 2*j + 1]);
        acc0[j] = b; acc1[j] = b;
    }

    #pragma unroll 1
    for (int fc = 0; fc < FN/4; ++fc) {
        const float4 u0 = h40[fc], u1 = h41[fc];
        const float* wk = sW2t + (4*fc)*FN + gh*32;
        K_STEP32(acc0, acc1, u0.x, u1.x, wk + 0*FN);
        K_STEP32(acc0, acc1, u0.y, u1.y, wk + 1*FN);
        K_STEP32(acc0, acc1, u0.z, u1.z, wk + 2*FN);
        K_STEP32(acc0, acc1, u0.w, u1.w, wk + 3*FN);
    }

    if (n0 < NN) {
        float* op = out + (((size_t)p*NN + n0)*CC + c)*FN + gh*32;
        #pragma unroll
        for (int q = 0; q < 16; q += 2) {
            float a0, a1, b0, b1;
            UNPACK_F32X2(a0, a1, acc0[q]);
            UNPACK_F32X2(b0, b1, acc0[q+1]);
            *(float4*)(op + 2*q) =
                make_float4(tanhf(a0), tanhf(a1), tanhf(b0), tanhf(b1));
        }
    }
    if (n1 < NN) {
        float* op = out + (((size_t)p*NN + n1)*CC + c)*FN + gh*32;
        #pragma unroll
        for (int q = 0; q < 16; q += 2) {
            float a0, a1, b0, b1;
            UNPACK_F32X2(a0, a1, acc1[q]);
            UNPACK_F32X2(b0, b1, acc1[q+1]);
            *(float4*)(op + 2*q) =
                make_float4(tanhf(a0), tanhf(a1), tanhf(b0), tanhf(b1));
        }
    }
}

extern "C" void kernel_launch(void* const* d_in, const int* in_sizes, int n_in,
                              void* d_out, int out_size) {
    const float* x   = (const float*)d_in[0];
    const void*  ei  = d_in[1];
    const float* We1 = (const float*)d_in[2];
    const float* be1 = (const float*)d_in[3];
    const float* We2 = (const float*)d_in[4];
    const float* be2 = (const float*)d_in[5];
    const float* Wn1 = (const float*)d_in[6];
    const float* bn1 = (const float*)d_in[7];
    const float* Wn2 = (const float*)d_in[8];
    const float* bn2 = (const float*)d_in[9];
    float* out = (float*)d_out;

    detect_kernel<<<1, 1>>>(ei);
    zero_kernel<<<1024, 256>>>();

    dim3 gp((NN*CC + 255)/256, PP);
    pre_kernel<<<gp, 256>>>(x, We1, be1);

    dim3 ge(EE/256, PP);
    edge_kernel<<<ge, 256>>>(x, ei, We2, be2);

    dim3 gn((NN + 255)/256, CC, PP);
    node1_kernel<<<gn, 256>>>(x, Wn1, bn1);
    node2_kernel<<<gn, 256>>>(Wn2, bn2, out);
}

// round 10
// speedup vs baseline: 1.5379x; 1.2806x over previous
#include <cuda_runtime.h>
#include <math.h>

#define PP 3
#define NN 50000
#define EE 256000
#define CC 5
#define FF 68
#define FE 16
#define FN 64
#define F2 (2*FF)   // 136

typedef unsigned int uint;

__device__ __forceinline__ float tanh_fast(float x) {
    float y; asm("tanh.approx.f32 %0, %1;" : "=f"(y) : "f"(x)); return y;
}
__device__ __forceinline__ uint f2tf32(float v) {
    uint t; asm("cvt.rna.tf32.f32 %0, %1;" : "=r"(t) : "f"(v)); return t;
}
__device__ __forceinline__ void mma_tf32(float* c, const uint* a, uint b0, uint b1) {
    asm volatile("mma.sync.aligned.m16n8k8.row.col.f32.tf32.tf32.f32 "
        "{%0,%1,%2,%3}, {%4,%5,%6,%7}, {%8,%9}, {%0,%1,%2,%3};"
        : "+f"(c[0]), "+f"(c[1]), "+f"(c[2]), "+f"(c[3])
        : "r"(a[0]), "r"(a[1]), "r"(a[2]), "r"(a[3]), "r"(b0), "r"(b1));
}
__device__ __forceinline__ void red4(float* addr, float a, float b, float c, float d) {
    asm volatile("red.global.add.v4.f32 [%0], {%1,%2,%3,%4};"
                 :: "l"(addr), "f"(a), "f"(b), "f"(c), "f"(d) : "memory");
}

// Scratch: A/B gate partials 48MB each; P,Y,S node partials 192MB each
__device__ __align__(16) float g_A[(size_t)PP*NN*CC*FE];
__device__ __align__(16) float g_B[(size_t)PP*NN*CC*FE];
__device__ __align__(16) float g_P[(size_t)PP*NN*CC*FN];
__device__ __align__(16) float g_Y[(size_t)PP*NN*CC*FN];
__device__ __align__(16) float g_S[(size_t)PP*NN*CC*FN];

__global__ void zero_kernel() {
    const size_t total = (size_t)PP*NN*CC*FN/4;
    float4* p = (float4*)g_S;
    const float4 z = make_float4(0.f, 0.f, 0.f, 0.f);
    for (size_t i = (size_t)blockIdx.x*blockDim.x + threadIdx.x; i < total;
         i += (size_t)gridDim.x*blockDim.x)
        p[i] = z;
}

// ---------------------------------------------------------------------------
// G1: fused per-node GEMM  [A(16)|B(16)|P(64)|Y(64)] = x . Wf^T  (tf32 MMA)
//   A = We1[:, :68].x + be1      (edge gate, x_i side)
//   B = We1[:, 68:].x            (edge gate, x_j side)
//   P = Wn1[:, :68].x + bn1      (node layer1, x side)
//   Y = Wn1[:, 68:].x            (node layer1, aggr side, pushed through scatter)
// Block = 128 thr, tile = 64 nodes x 160 outs, K = 68 padded to 72.
// ---------------------------------------------------------------------------
#define XS_STRIDE 76
#define WS_STRIDE 168

__global__ __launch_bounds__(128) void g1_kernel(
    const float* __restrict__ x,
    const float* __restrict__ We1, const float* __restrict__ be1,
    const float* __restrict__ Wn1, const float* __restrict__ bn1)
{
    __shared__ __align__(16) uint XS[64*XS_STRIDE];    // 19456 B
    __shared__ __align__(16) uint WS[72*WS_STRIDE];    // 48384 B
    __shared__ float sbias[160];

    const int c = blockIdx.y;
    const int p = blockIdx.z;
    const int tid = threadIdx.x;
    const int n0 = blockIdx.x * 64;

    // ---- stage fused weights (transposed to [k][g], tf32, zero-padded k>=68)
    const size_t eoff = ((size_t)p*CC + c)*FE*F2;
    const size_t noff = ((size_t)p*CC + c)*FN*F2;
    for (int i = tid; i < 72*160; i += 128) {
        const int k = i / 160, g = i % 160;
        float v = 0.f;
        if (k < FF) {
            if (g < 16)      v = We1[eoff + (size_t)g*F2 + k];
            else if (g < 32) v = We1[eoff + (size_t)(g-16)*F2 + FF + k];
            else if (g < 96) v = Wn1[noff + (size_t)(g-32)*F2 + k];
            else             v = Wn1[noff + (size_t)(g-96)*F2 + FF + k];
        }
        WS[k*WS_STRIDE + g] = f2tf32(v);
    }
    for (int g = tid; g < 160; g += 128) {
        float b = 0.f;
        if (g < 16)                 b = be1[(p*CC + c)*FE + g];
        else if (g >= 32 && g < 96) b = bn1[(p*CC + c)*FN + (g-32)];
        sbias[g] = b;
    }
    // ---- stage X tile (64 rows x 68 cols, tf32), zero pad rows>=NN, cols 68..71
    for (int i = tid; i < 64*17; i += 128) {
        const int r = i / 17, f4 = i % 17;
        const int n = n0 + r;
        float4 v = make_float4(0.f, 0.f, 0.f, 0.f);
        if (n < NN)
            v = *(const float4*)(x + (((size_t)p*NN + n)*CC + c)*FF + f4*4);
        uint4 t;
        t.x = f2tf32(v.x); t.y = f2tf32(v.y); t.z = f2tf32(v.z); t.w = f2tf32(v.w);
        *(uint4*)&XS[r*XS_STRIDE + f4*4] = t;
    }
    for (int i = tid; i < 64*4; i += 128) {
        const int r = i >> 2, k = FF + (i & 3);
        XS[r*XS_STRIDE + k] = 0;
    }
    __syncthreads();

    const int warp = tid >> 5, lane = tid & 31;
    const int rowBase = (warp & 1) * 32;    // 2 row groups of 32
    const int colBase = (warp >> 1) * 80;   // 2 col groups of 80
    const int r  = lane >> 2;
    const int kk = lane & 3;

    float acc[2][10][4];
    #pragma unroll
    for (int mt = 0; mt < 2; ++mt)
        #pragma unroll
        for (int nt = 0; nt < 10; ++nt)
            #pragma unroll
            for (int q = 0; q < 4; ++q) acc[mt][nt][q] = 0.f;

    #pragma unroll 1
    for (int ks = 0; ks < 9; ++ks) {
        uint a[2][4];
        #pragma unroll
        for (int mt = 0; mt < 2; ++mt) {
            const int rb = rowBase + mt*16;
            a[mt][0] = XS[(rb + r    )*XS_STRIDE + ks*8 + kk    ];
            a[mt][1] = XS[(rb + r + 8)*XS_STRIDE + ks*8 + kk    ];
            a[mt][2] = XS[(rb + r    )*XS_STRIDE + ks*8 + kk + 4];
            a[mt][3] = XS[(rb + r + 8)*XS_STRIDE + ks*8 + kk + 4];
        }
        #pragma unroll
        for (int nt = 0; nt < 10; ++nt) {
            const uint b0 = WS[(ks*8 + kk    )*WS_STRIDE + colBase + nt*8 + r];
            const uint b1 = WS[(ks*8 + kk + 4)*WS_STRIDE + colBase + nt*8 + r];
            mma_tf32(acc[0][nt], a[0], b0, b1);
            mma_tf32(acc[1][nt], a[1], b0, b1);
        }
    }

    // ---- writeback: route cols to A/B/P/Y with bias
    const size_t pnc = (size_t)p*NN;
    #pragma unroll
    for (int mt = 0; mt < 2; ++mt) {
        #pragma unroll
        for (int half = 0; half < 2; ++half) {
            const int n = n0 + rowBase + mt*16 + r + half*8;
            if (n >= NN) continue;
            const size_t base = (pnc + n)*CC + c;
            #pragma unroll
            for (int nt = 0; nt < 10; ++nt) {
                const int g = colBase + nt*8 + kk*2;
                float2 v;
                v.x = acc[mt][nt][half*2 + 0] + sbias[g];
                v.y = acc[mt][nt][half*2 + 1] + sbias[g+1];
                if (g < 16)      *(float2*)(g_A + base*FE + g)      = v;
                else if (g < 32) *(float2*)(g_B + base*FE + (g-16)) = v;
                else if (g < 96) *(float2*)(g_P + base*FN + (g-32)) = v;
                else             *(float2*)(g_Y + base*FN + (g-96)) = v;
            }
        }
    }
}

// ---------------------------------------------------------------------------
// Edge kernel: gather A[dst]+B[src], tanh gate, class softmax,
// scatter w * Y[src] into S[dst] (layer-1 pushed through the aggregation).
// ---------------------------------------------------------------------------
__global__ __launch_bounds__(256) void edge_kernel(
    const void* __restrict__ ei,
    const float* __restrict__ We2, const float* __restrict__ be2)
{
    __shared__ float sW2[CC*FE];
    __shared__ float sb2[CC];

    const int p = blockIdx.y;
    for (int i = threadIdx.x; i < CC*FE; i += blockDim.x)
        sW2[i] = We2[p*CC*FE + i];
    if (threadIdx.x < CC) sb2[threadIdx.x] = be2[p*CC + threadIdx.x];
    __syncthreads();

    // dtype detection (uniform across all threads): int64 data has valid ids
    const long long* q = (const long long*)ei;
    int ok = 1;
    #pragma unroll
    for (int i = 0; i < 16; ++i) {
        const long long v = q[i];
        ok &= (v >= 0) && (v < NN);
    }

    const long long* ei64 = (const long long*)ei;
    const int*       ei32 = (const int*)ei;
    const size_t base = (size_t)p*2*EE;

    const int e = blockIdx.x*blockDim.x + threadIdx.x;   // EE % 256 == 0
    int s, d;
    if (ok) {
        s = (int)ei64[base + e];
        d = (int)ei64[base + EE + e];
    } else {
        s = ei32[base + e];
        d = ei32[base + EE + e];
    }

    const float4* Ad = (const float4*)(g_A + ((size_t)p*NN + d)*(CC*FE));
    const float4* Bs = (const float4*)(g_B + ((size_t)p*NN + s)*(CC*FE));

    float lg[CC];
    #pragma unroll
    for (int c = 0; c < CC; ++c) {
        float l = sb2[c];
        #pragma unroll
        for (int j = 0; j < 4; ++j) {
            const float4 a = Ad[c*4 + j];
            const float4 b = Bs[c*4 + j];
            l += tanh_fast(a.x + b.x) * sW2[c*FE + 4*j + 0]
               + tanh_fast(a.y + b.y) * sW2[c*FE + 4*j + 1]
               + tanh_fast(a.z + b.z) * sW2[c*FE + 4*j + 2]
               + tanh_fast(a.w + b.w) * sW2[c*FE + 4*j + 3];
        }
        lg[c] = l;
    }

    float mx = lg[0];
    #pragma unroll
    for (int c = 1; c < CC; ++c) mx = fmaxf(mx, lg[c]);
    float w[CC];
    float sum = 0.f;
    #pragma unroll
    for (int c = 0; c < CC; ++c) { w[c] = expf(lg[c] - mx); sum += w[c]; }
    const float inv = 1.f / sum;

    const float* Ys = g_Y + ((size_t)p*NN + s)*(CC*FN);
    float* Sd       = g_S + ((size_t)p*NN + d)*(CC*FN);
    #pragma unroll
    for (int c = 0; c < CC; ++c) {
        const float wc = w[c] * inv;
        const float4* yv = (const float4*)(Ys + c*FN);
        float* sp = Sd + c*FN;
        #pragma unroll 1
        for (int fc = 0; fc < FN/4; ++fc) {
            const float4 v = yv[fc];
            red4(sp + 4*fc, wc*v.x, wc*v.y, wc*v.z, wc*v.w);
        }
    }
}

// ---------------------------------------------------------------------------
// G2: h = tanh(P + S); out = tanh(h . W2^T + b2)   (tf32 MMA, 64x64, K=64)
// Block = 128 thr, tile = 64 nodes x 64 outs.
// ---------------------------------------------------------------------------
#define HS_STRIDE 68
#define W2_STRIDE 72

__global__ __launch_bounds__(128) void g2_kernel(
    const float* __restrict__ Wn2, const float* __restrict__ bn2,
    float* __restrict__ out)
{
    __shared__ __align__(16) uint HS[64*HS_STRIDE];    // 17408 B
    __shared__ __align__(16) uint W2S[64*W2_STRIDE];   // 18432 B
    __shared__ float sb2[FN];

    const int c = blockIdx.y;
    const int p = blockIdx.z;
    const int tid = threadIdx.x;
    const int n0 = blockIdx.x * 64;

    const size_t woff = ((size_t)p*CC + c)*FN*FN;
    for (int i = tid; i < FN*FN; i += 128) {
        const int k = i >> 6, g = i & 63;
        W2S[k*W2_STRIDE + g] = f2tf32(Wn2[woff + (size_t)g*FN + k]);
    }
    if (tid < FN) sb2[tid] = bn2[(p*CC + c)*FN + tid];

    for (int i = tid; i < 64*16; i += 128) {
        const int r = i >> 4, f4 = i & 15;
        const int n = n0 + r;
        uint4 t = make_uint4(0, 0, 0, 0);
        if (n < NN) {
            const size_t base = (((size_t)p*NN + n)*CC + c)*FN + f4*4;
            const float4 pv = *(const float4*)(g_P + base);
            const float4 sv = *(const float4*)(g_S + base);
            t.x = f2tf32(tanh_fast(pv.x + sv.x));
            t.y = f2tf32(tanh_fast(pv.y + sv.y));
            t.z = f2tf32(tanh_fast(pv.z + sv.z));
            t.w = f2tf32(tanh_fast(pv.w + sv.w));
        }
        *(uint4*)&HS[r*HS_STRIDE + f4*4] = t;
    }
    __syncthreads();

    const int warp = tid >> 5, lane = tid & 31;
    const int rowBase = (warp & 1) * 32;
    const int colBase = (warp >> 1) * 32;
    const int r  = lane >> 2;
    const int kk = lane & 3;

    float acc[2][4][4];
    #pragma unroll
    for (int mt = 0; mt < 2; ++mt)
        #pragma unroll
        for (int nt = 0; nt < 4; ++nt)
            #pragma unroll
            for (int q = 0; q < 4; ++q) acc[mt][nt][q] = 0.f;

    #pragma unroll 1
    for (int ks = 0; ks < 8; ++ks) {
        uint a[2][4];
        #pragma unroll
        for (int mt = 0; mt < 2; ++mt) {
            const int rb = rowBase + mt*16;
            a[mt][0] = HS[(rb + r    )*HS_STRIDE + ks*8 + kk    ];
            a[mt][1] = HS[(rb + r + 8)*HS_STRIDE + ks*8 + kk    ];
            a[mt][2] = HS[(rb + r    )*HS_STRIDE + ks*8 + kk + 4];
            a[mt][3] = HS[(rb + r + 8)*HS_STRIDE + ks*8 + kk + 4];
        }
        #pragma unroll
        for (int nt = 0; nt < 4; ++nt) {
            const uint b0 = W2S[(ks*8 + kk    )*W2_STRIDE + colBase + nt*8 + r];
            const uint b1 = W2S[(ks*8 + kk + 4)*W2_STRIDE + colBase + nt*8 + r];
            mma_tf32(acc[0][nt], a[0], b0, b1);
            mma_tf32(acc[1][nt], a[1], b0, b1);
        }
    }

    #pragma unroll
    for (int mt = 0; mt < 2; ++mt) {
        #pragma unroll
        for (int half = 0; half < 2; ++half) {
            const int n = n0 + rowBase + mt*16 + r + half*8;
            if (n >= NN) continue;
            float* op = out + (((size_t)p*NN + n)*CC + c)*FN;
            #pragma unroll
            for (int nt = 0; nt < 4; ++nt) {
                const int g = colBase + nt*8 + kk*2;
                float2 v;
                v.x = tanhf(acc[mt][nt][half*2 + 0] + sb2[g]);
                v.y = tanhf(acc[mt][nt][half*2 + 1] + sb2[g+1]);
                *(float2*)(op + g) = v;
            }
        }
    }
}

extern "C" void kernel_launch(void* const* d_in, const int* in_sizes, int n_in,
                              void* d_out, int out_size) {
    const float* x   = (const float*)d_in[0];
    const void*  ei  = d_in[1];
    const float* We1 = (const float*)d_in[2];
    const float* be1 = (const float*)d_in[3];
    const float* We2 = (const float*)d_in[4];
    const float* be2 = (const float*)d_in[5];
    const float* Wn1 = (const float*)d_in[6];
    const float* bn1 = (const float*)d_in[7];
    const float* Wn2 = (const float*)d_in[8];
    const float* bn2 = (const float*)d_in[9];
    float* out = (float*)d_out;

    dim3 gg((NN + 63)/64, CC, PP);
    g1_kernel<<<gg, 128>>>(x, We1, be1, Wn1, bn1);

    zero_kernel<<<1024, 256>>>();

    dim3 ge(EE/256, PP);
    edge_kernel<<<ge, 256>>>(ei, We2, be2);

    g2_kernel<<<gg, 128>>>(Wn2, bn2, out);
}

// round 11
// speedup vs baseline: 2.3244x; 1.5114x over previous
#include <cuda_runtime.h>
#include <math.h>

#define PP 3
#define NN 50000
#define EE 256000
#define CC 5
#define FF 68
#define FE 16
#define FN 64
#define F2 (2*FF)   // 136

typedef unsigned int uint;

__device__ __forceinline__ float tanh_fast(float x) {
    float y; asm("tanh.approx.f32 %0, %1;" : "=f"(y) : "f"(x)); return y;
}
__device__ __forceinline__ uint f2tf32(float v) {
    uint t; asm("cvt.rna.tf32.f32 %0, %1;" : "=r"(t) : "f"(v)); return t;
}
__device__ __forceinline__ void mma_tf32(float* c, const uint* a, uint b0, uint b1) {
    asm volatile("mma.sync.aligned.m16n8k8.row.col.f32.tf32.tf32.f32 "
        "{%0,%1,%2,%3}, {%4,%5,%6,%7}, {%8,%9}, {%0,%1,%2,%3};"
        : "+f"(c[0]), "+f"(c[1]), "+f"(c[2]), "+f"(c[3])
        : "r"(a[0]), "r"(a[1]), "r"(a[2]), "r"(a[3]), "r"(b0), "r"(b1));
}
__device__ __forceinline__ void red4(float* addr, float a, float b, float c, float d) {
    asm volatile("red.global.add.v4.f32 [%0], {%1,%2,%3,%4};"
                 :: "l"(addr), "f"(a), "f"(b), "f"(c), "f"(d) : "memory");
}

// Scratch
__device__ __align__(16) float g_A[(size_t)PP*NN*CC*FE];
__device__ __align__(16) float g_B[(size_t)PP*NN*CC*FE];
__device__ __align__(16) float g_P[(size_t)PP*NN*CC*FN];
__device__ __align__(16) float g_Y[(size_t)PP*NN*CC*FN];
__device__ __align__(16) float g_S[(size_t)PP*NN*CC*FN];
// Pre-transposed, tf32-converted, k-interleaved weights
__device__ __align__(16) uint g_W1t[(size_t)PP*CC*160*72];
__device__ __align__(16) uint g_W2t[(size_t)PP*CC*64*64];

__global__ void zero_kernel() {
    const size_t total = (size_t)PP*NN*CC*FN/4;
    float4* p = (float4*)g_S;
    const float4 z = make_float4(0.f, 0.f, 0.f, 0.f);
    for (size_t i = (size_t)blockIdx.x*blockDim.x + threadIdx.x; i < total;
         i += (size_t)gridDim.x*blockDim.x)
        p[i] = z;
}

// ---------------------------------------------------------------------------
// wprep: build fused+transposed tf32 weight images, k-interleaved so that
// mma fragment pairs (kk, kk+4) are adjacent (storage order k0,k4,k1,k5,...).
//   W1t[pc][g=160][kperm=72]: g in [A(16)|B(16)|P(64)|Y(64)] order, k zero-pad
//   W2t[pc][g=64][kperm=64]
// ---------------------------------------------------------------------------
__global__ __launch_bounds__(256) void wprep_kernel(
    const float* __restrict__ We1, const float* __restrict__ Wn1,
    const float* __restrict__ Wn2)
{
    const int pc = blockIdx.x;   // p*CC + c
    const size_t eoff = (size_t)pc*FE*F2;
    const size_t noff = (size_t)pc*FN*F2;

    uint* w1 = g_W1t + (size_t)pc*160*72;
    for (int i = threadIdx.x; i < 160*72; i += blockDim.x) {
        const int g = i / 72, kp = i % 72;
        const int ks = kp >> 3, pos = kp & 7;
        const int k = ks*8 + (pos >> 1) + (pos & 1)*4;
        float v = 0.f;
        if (k < FF) {
            if (g < 16)      v = We1[eoff + (size_t)g*F2 + k];
            else if (g < 32) v = We1[eoff + (size_t)(g-16)*F2 + FF + k];
            else if (g < 96) v = Wn1[noff + (size_t)(g-32)*F2 + k];
            else             v = Wn1[noff + (size_t)(g-96)*F2 + FF + k];
        }
        w1[i] = f2tf32(v);
    }

    uint* w2 = g_W2t + (size_t)pc*64*64;
    const float* Wn2p = Wn2 + (size_t)pc*FN*FN;
    for (int i = threadIdx.x; i < 64*64; i += blockDim.x) {
        const int g = i >> 6, kp = i & 63;
        const int ks = kp >> 3, pos = kp & 7;
        const int k = ks*8 + (pos >> 1) + (pos & 1)*4;
        w2[i] = f2tf32(Wn2p[(size_t)g*FN + k]);
    }
}

// ---------------------------------------------------------------------------
// G1: [A|B|P|Y](160) = x(68) . Wf^T per (p,c), tf32 MMA.
// Block = 256 thr = 8 warps = 4 rowGroups(32) x 2 colGroups(80); 128 nodes.
// ---------------------------------------------------------------------------
#define XST 76
#define WST 76

__global__ __launch_bounds__(256, 2) void g1_kernel(
    const float* __restrict__ x,
    const float* __restrict__ be1, const float* __restrict__ bn1)
{
    extern __shared__ __align__(16) uint smem_u[];
    uint*  XS    = smem_u;                 // 128*76
    uint*  WS    = XS + 128*XST;           // 160*76
    float* sbias = (float*)(WS + 160*WST); // 160

    const int c = blockIdx.y, p = blockIdx.z, tid = threadIdx.x;
    const int n0 = blockIdx.x * 128;
    const int pc = p*CC + c;

    // weights: plain uint4 copy from pre-built image
    const uint* w1 = g_W1t + (size_t)pc*160*72;
    for (int i = tid; i < 160*18; i += 256) {
        const int g = i / 18, j = i % 18;
        *(uint4*)&WS[g*WST + j*4] = *(const uint4*)&w1[g*72 + j*4];
    }
    for (int g = tid; g < 160; g += 256) {
        float b = 0.f;
        if (g < 16)                 b = be1[pc*FE + g];
        else if (g >= 32 && g < 96) b = bn1[pc*FN + (g-32)];
        sbias[g] = b;
    }
    // X tile: 128 rows x 68 cols, tf32, k-interleaved
    for (int i = tid; i < 128*17; i += 256) {
        const int r = i / 17, f4 = i % 17;
        const int n = n0 + r;
        float4 v = make_float4(0.f, 0.f, 0.f, 0.f);
        if (n < NN)
            v = *(const float4*)(x + (((size_t)p*NN + n)*CC + c)*FF + f4*4);
        const int ks = f4 >> 1;
        uint* b = &XS[r*XST + ks*8 + (f4 & 1)];
        b[0] = f2tf32(v.x); b[2] = f2tf32(v.y);
        b[4] = f2tf32(v.z); b[6] = f2tf32(v.w);
    }
    for (int i = tid; i < 128*4; i += 256) {    // zero-pad k=68..71
        const int r = i >> 2, j = i & 3;
        XS[r*XST + 64 + 2*j + 1] = 0;
    }
    __syncthreads();

    const int warp = tid >> 5, lane = tid & 31;
    const int rowBase = (warp & 3) * 32;
    const int colBase = (warp >> 2) * 80;
    const int r  = lane >> 2;
    const int kk = lane & 3;

    float acc[2][10][4];
    #pragma unroll
    for (int mt = 0; mt < 2; ++mt)
        #pragma unroll
        for (int nt = 0; nt < 10; ++nt)
            #pragma unroll
            for (int q = 0; q < 4; ++q) acc[mt][nt][q] = 0.f;

    #pragma unroll 1
    for (int ks = 0; ks < 9; ++ks) {
        uint a[2][4];
        #pragma unroll
        for (int mt = 0; mt < 2; ++mt) {
            const int rb = rowBase + mt*16;
            const uint2 lo = *(const uint2*)&XS[(rb + r    )*XST + ks*8 + 2*kk];
            const uint2 hi = *(const uint2*)&XS[(rb + r + 8)*XST + ks*8 + 2*kk];
            a[mt][0] = lo.x; a[mt][1] = hi.x; a[mt][2] = lo.y; a[mt][3] = hi.y;
        }
        #pragma unroll
        for (int nt = 0; nt < 10; ++nt) {
            const uint2 b = *(const uint2*)&WS[(colBase + nt*8 + r)*WST + ks*8 + 2*kk];
            mma_tf32(acc[0][nt], a[0], b.x, b.y);
            mma_tf32(acc[1][nt], a[1], b.x, b.y);
        }
    }

    const size_t pnc = (size_t)p*NN;
    #pragma unroll
    for (int mt = 0; mt < 2; ++mt) {
        #pragma unroll
        for (int half = 0; half < 2; ++half) {
            const int n = n0 + rowBase + mt*16 + r + half*8;
            if (n >= NN) continue;
            const size_t base = (pnc + n)*CC + c;
            #pragma unroll
            for (int nt = 0; nt < 10; ++nt) {
                const int g = colBase + nt*8 + kk*2;
                float2 v;
                v.x = acc[mt][nt][half*2 + 0] + sbias[g];
                v.y = acc[mt][nt][half*2 + 1] + sbias[g+1];
                if (g < 16)      *(float2*)(g_A + base*FE + g)      = v;
                else if (g < 32) *(float2*)(g_B + base*FE + (g-16)) = v;
                else if (g < 96) *(float2*)(g_P + base*FN + (g-32)) = v;
                else             *(float2*)(g_Y + base*FN + (g-96)) = v;
            }
        }
    }
}

// ---------------------------------------------------------------------------
// Edge kernel: gather A[dst]+B[src], tanh gate, class softmax,
// scatter w * Y[src] into S[dst].
// ---------------------------------------------------------------------------
__global__ __launch_bounds__(256) void edge_kernel(
    const void* __restrict__ ei,
    const float* __restrict__ We2, const float* __restrict__ be2)
{
    __shared__ float sW2[CC*FE];
    __shared__ float sb2[CC];

    const int p = blockIdx.y;
    for (int i = threadIdx.x; i < CC*FE; i += blockDim.x)
        sW2[i] = We2[p*CC*FE + i];
    if (threadIdx.x < CC) sb2[threadIdx.x] = be2[p*CC + threadIdx.x];
    __syncthreads();

    const long long* q = (const long long*)ei;
    int ok = 1;
    #pragma unroll
    for (int i = 0; i < 16; ++i) {
        const long long v = q[i];
        ok &= (v >= 0) && (v < NN);
    }

    const long long* ei64 = (const long long*)ei;
    const int*       ei32 = (const int*)ei;
    const size_t base = (size_t)p*2*EE;

    const int e = blockIdx.x*blockDim.x + threadIdx.x;
    int s, d;
    if (ok) {
        s = (int)ei64[base + e];
        d = (int)ei64[base + EE + e];
    } else {
        s = ei32[base + e];
        d = ei32[base + EE + e];
    }

    const float4* Ad = (const float4*)(g_A + ((size_t)p*NN + d)*(CC*FE));
    const float4* Bs = (const float4*)(g_B + ((size_t)p*NN + s)*(CC*FE));

    float lg[CC];
    #pragma unroll
    for (int c = 0; c < CC; ++c) {
        float l = sb2[c];
        #pragma unroll
        for (int j = 0; j < 4; ++j) {
            const float4 a = Ad[c*4 + j];
            const float4 b = Bs[c*4 + j];
            l += tanh_fast(a.x + b.x) * sW2[c*FE + 4*j + 0]
               + tanh_fast(a.y + b.y) * sW2[c*FE + 4*j + 1]
               + tanh_fast(a.z + b.z) * sW2[c*FE + 4*j + 2]
               + tanh_fast(a.w + b.w) * sW2[c*FE + 4*j + 3];
        }
        lg[c] = l;
    }

    float mx = lg[0];
    #pragma unroll
    for (int c = 1; c < CC; ++c) mx = fmaxf(mx, lg[c]);
    float w[CC];
    float sum = 0.f;
    #pragma unroll
    for (int c = 0; c < CC; ++c) { w[c] = expf(lg[c] - mx); sum += w[c]; }
    const float inv = 1.f / sum;

    const float* Ys = g_Y + ((size_t)p*NN + s)*(CC*FN);
    float* Sd       = g_S + ((size_t)p*NN + d)*(CC*FN);
    #pragma unroll
    for (int c = 0; c < CC; ++c) {
        const float wc = w[c] * inv;
        const float4* yv = (const float4*)(Ys + c*FN);
        float* sp = Sd + c*FN;
        #pragma unroll 1
        for (int fc = 0; fc < FN/4; ++fc) {
            const float4 v = yv[fc];
            red4(sp + 4*fc, wc*v.x, wc*v.y, wc*v.z, wc*v.w);
        }
    }
}

// ---------------------------------------------------------------------------
// G2: h = tanh(P + S); out = tanh(h . W2^T + b2), tf32 MMA.
// Block = 256 thr = 8 warps = 4 rowGroups(32) x 2 colGroups(32); 128 nodes.
// ---------------------------------------------------------------------------
#define HST 68
#define W2T 68

__global__ __launch_bounds__(256, 2) void g2_kernel(
    const float* __restrict__ bn2, float* __restrict__ out)
{
    extern __shared__ __align__(16) uint smem_u[];
    uint*  HS  = smem_u;                // 128*68
    uint*  W2S = HS + 128*HST;          // 64*68
    float* sb2 = (float*)(W2S + 64*W2T);

    const int c = blockIdx.y, p = blockIdx.z, tid = threadIdx.x;
    const int n0 = blockIdx.x * 128;
    const int pc = p*CC + c;

    const uint* w2 = g_W2t + (size_t)pc*64*64;
    for (int i = tid; i < 64*16; i += 256) {
        const int g = i >> 4, j = i & 15;
        *(uint4*)&W2S[g*W2T + j*4] = *(const uint4*)&w2[g*64 + j*4];
    }
    if (tid < FN) sb2[tid] = bn2[pc*FN + tid];

    for (int i = tid; i < 128*16; i += 256) {
        const int r = i >> 4, f4 = i & 15;
        const int n = n0 + r;
        float4 hv = make_float4(0.f, 0.f, 0.f, 0.f);
        if (n < NN) {
            const size_t base = (((size_t)p*NN + n)*CC + c)*FN + f4*4;
            const float4 pv = *(const float4*)(g_P + base);
            const float4 sv = *(const float4*)(g_S + base);
            hv.x = tanh_fast(pv.x + sv.x);
            hv.y = tanh_fast(pv.y + sv.y);
            hv.z = tanh_fast(pv.z + sv.z);
            hv.w = tanh_fast(pv.w + sv.w);
        }
        const int ks = f4 >> 1;
        uint* b = &HS[r*HST + ks*8 + (f4 & 1)];
        b[0] = f2tf32(hv.x); b[2] = f2tf32(hv.y);
        b[4] = f2tf32(hv.z); b[6] = f2tf32(hv.w);
    }
    __syncthreads();

    const int warp = tid >> 5, lane = tid & 31;
    const int rowBase = (warp & 3) * 32;
    const int colBase = (warp >> 2) * 32;
    const int r  = lane >> 2;
    const int kk = lane & 3;

    float acc[2][4][4];
    #pragma unroll
    for (int mt = 0; mt < 2; ++mt)
        #pragma unroll
        for (int nt = 0; nt < 4; ++nt)
            #pragma unroll
            for (int q = 0; q < 4; ++q) acc[mt][nt][q] = 0.f;

    #pragma unroll 1
    for (int ks = 0; ks < 8; ++ks) {
        uint a[2][4];
        #pragma unroll
        for (int mt = 0; mt < 2; ++mt) {
            const int rb = rowBase + mt*16;
            const uint2 lo = *(const uint2*)&HS[(rb + r    )*HST + ks*8 + 2*kk];
            const uint2 hi = *(const uint2*)&HS[(rb + r + 8)*HST + ks*8 + 2*kk];
            a[mt][0] = lo.x; a[mt][1] = hi.x; a[mt][2] = lo.y; a[mt][3] = hi.y;
        }
        #pragma unroll
        for (int nt = 0; nt < 4; ++nt) {
            const uint2 b = *(const uint2*)&W2S[(colBase + nt*8 + r)*W2T + ks*8 + 2*kk];
            mma_tf32(acc[0][nt], a[0], b.x, b.y);
            mma_tf32(acc[1][nt], a[1], b.x, b.y);
        }
    }

    #pragma unroll
    for (int mt = 0; mt < 2; ++mt) {
        #pragma unroll
        for (int half = 0; half < 2; ++half) {
            const int n = n0 + rowBase + mt*16 + r + half*8;
            if (n >= NN) continue;
            float* op = out + (((size_t)p*NN + n)*CC + c)*FN;
            #pragma unroll
            for (int nt = 0; nt < 4; ++nt) {
                const int g = colBase + nt*8 + kk*2;
                float2 v;
                v.x = tanhf(acc[mt][nt][half*2 + 0] + sb2[g]);
                v.y = tanhf(acc[mt][nt][half*2 + 1] + sb2[g+1]);
                *(float2*)(op + g) = v;
            }
        }
    }
}

extern "C" void kernel_launch(void* const* d_in, const int* in_sizes, int n_in,
                              void* d_out, int out_size) {
    const float* x   = (const float*)d_in[0];
    const void*  ei  = d_in[1];
    const float* We1 = (const float*)d_in[2];
    const float* be1 = (const float*)d_in[3];
    const float* We2 = (const float*)d_in[4];
    const float* be2 = (const float*)d_in[5];
    const float* Wn1 = (const float*)d_in[6];
    const float* bn1 = (const float*)d_in[7];
    const float* Wn2 = (const float*)d_in[8];
    const float* bn2 = (const float*)d_in[9];
    float* out = (float*)d_out;

    const int smem1 = (128*XST + 160*WST)*4 + 160*4;   // 88192 B
    const int smem2 = (128*HST + 64*W2T)*4 + 64*4;     // 52480 B
    cudaFuncSetAttribute(g1_kernel,
                         cudaFuncAttributeMaxDynamicSharedMemorySize, smem1);
    cudaFuncSetAttribute(g2_kernel,
                         cudaFuncAttributeMaxDynamicSharedMemorySize, smem2);

    wprep_kernel<<<PP*CC, 256>>>(We1, Wn1, Wn2);
    zero_kernel<<<1024, 256>>>();

    dim3 gg((NN + 127)/128, CC, PP);
    g1_kernel<<<gg, 256, smem1>>>(x, be1, bn1);

    dim3 ge(EE/256, PP);
    edge_kernel<<<ge, 256>>>(ei, We2, be2);

    g2_kernel<<<gg, 256, smem2>>>(bn2, out);
}

// round 12
// speedup vs baseline: 3.6021x; 1.5497x over previous
#include <cuda_runtime.h>
#include <math.h>

#define PP 3
#define NN 50000
#define EE 256000
#define CC 5
#define FF 68
#define FE 16
#define FN 64
#define F2 (2*FF)   // 136
#define SLOTS 32

typedef unsigned int uint;

__device__ __forceinline__ float tanh_fast(float x) {
    float y; asm("tanh.approx.f32 %0, %1;" : "=f"(y) : "f"(x)); return y;
}
__device__ __forceinline__ uint f2tf32(float v) {
    uint t; asm("cvt.rna.tf32.f32 %0, %1;" : "=r"(t) : "f"(v)); return t;
}
__device__ __forceinline__ void mma_tf32(float* c, const uint* a, uint b0, uint b1) {
    asm volatile("mma.sync.aligned.m16n8k8.row.col.f32.tf32.tf32.f32 "
        "{%0,%1,%2,%3}, {%4,%5,%6,%7}, {%8,%9}, {%0,%1,%2,%3};"
        : "+f"(c[0]), "+f"(c[1]), "+f"(c[2]), "+f"(c[3])
        : "r"(a[0]), "r"(a[1]), "r"(a[2]), "r"(a[3]), "r"(b0), "r"(b1));
}

// Scratch
__device__ __align__(16) float g_A[(size_t)PP*NN*CC*FE];         // 48 MB
__device__ __align__(16) float g_B[(size_t)PP*NN*CC*FE];         // 48 MB
__device__ __align__(16) float g_P[(size_t)PP*NN*CC*FN];         // 192 MB
__device__ __align__(16) float g_Y[(size_t)PP*NN*CC*FN];         // 192 MB
__device__ __align__(16) uint  g_H[(size_t)PP*NN*CC*FN];         // 192 MB (tf32)
__device__ __align__(16) float g_bkt[(size_t)PP*NN*SLOTS*8];     // 154 MB
__device__ int g_deg[PP*NN];
// Pre-transposed, tf32, k-interleaved weights
__device__ __align__(16) uint g_W1t[(size_t)PP*CC*160*72];
__device__ __align__(16) uint g_W2t[(size_t)PP*CC*64*64];

__global__ void zero_deg_kernel() {
    const int i = blockIdx.x*blockDim.x + threadIdx.x;
    if (i < PP*NN) g_deg[i] = 0;
}

// ---------------------------------------------------------------------------
// wprep: fused+transposed tf32 weight images, k-interleaved (k0,k4,k1,k5,...)
// ---------------------------------------------------------------------------
__global__ __launch_bounds__(256) void wprep_kernel(
    const float* __restrict__ We1, const float* __restrict__ Wn1,
    const float* __restrict__ Wn2)
{
    const int pc = blockIdx.x;
    const size_t eoff = (size_t)pc*FE*F2;
    const size_t noff = (size_t)pc*FN*F2;

    uint* w1 = g_W1t + (size_t)pc*160*72;
    for (int i = threadIdx.x; i < 160*72; i += blockDim.x) {
        const int g = i / 72, kp = i % 72;
        const int ks = kp >> 3, pos = kp & 7;
        const int k = ks*8 + (pos >> 1) + (pos & 1)*4;
        float v = 0.f;
        if (k < FF) {
            if (g < 16)      v = We1[eoff + (size_t)g*F2 + k];
            else if (g < 32) v = We1[eoff + (size_t)(g-16)*F2 + FF + k];
            else if (g < 96) v = Wn1[noff + (size_t)(g-32)*F2 + k];
            else             v = Wn1[noff + (size_t)(g-96)*F2 + FF + k];
        }
        w1[i] = f2tf32(v);
    }

    uint* w2 = g_W2t + (size_t)pc*64*64;
    const float* Wn2p = Wn2 + (size_t)pc*FN*FN;
    for (int i = threadIdx.x; i < 64*64; i += blockDim.x) {
        const int g = i >> 6, kp = i & 63;
        const int ks = kp >> 3, pos = kp & 7;
        const int k = ks*8 + (pos >> 1) + (pos & 1)*4;
        w2[i] = f2tf32(Wn2p[(size_t)g*FN + k]);
    }
}

// ---------------------------------------------------------------------------
// G1: [A|B|P|Y](160) = x(68) . Wf^T per (p,c), tf32 MMA. 128 nodes/block.
// ---------------------------------------------------------------------------
#define XST 76
#define WST 76

__global__ __launch_bounds__(256, 2) void g1_kernel(
    const float* __restrict__ x,
    const float* __restrict__ be1, const float* __restrict__ bn1)
{
    extern __shared__ __align__(16) uint smem_u[];
    uint*  XS    = smem_u;
    uint*  WS    = XS + 128*XST;
    float* sbias = (float*)(WS + 160*WST);

    const int c = blockIdx.y, p = blockIdx.z, tid = threadIdx.x;
    const int n0 = blockIdx.x * 128;
    const int pc = p*CC + c;

    const uint* w1 = g_W1t + (size_t)pc*160*72;
    for (int i = tid; i < 160*18; i += 256) {
        const int g = i / 18, j = i % 18;
        *(uint4*)&WS[g*WST + j*4] = *(const uint4*)&w1[g*72 + j*4];
    }
    for (int g = tid; g < 160; g += 256) {
        float b = 0.f;
        if (g < 16)                 b = be1[pc*FE + g];
        else if (g >= 32 && g < 96) b = bn1[pc*FN + (g-32)];
        sbias[g] = b;
    }
    for (int i = tid; i < 128*17; i += 256) {
        const int r = i / 17, f4 = i % 17;
        const int n = n0 + r;
        float4 v = make_float4(0.f, 0.f, 0.f, 0.f);
        if (n < NN)
            v = *(const float4*)(x + (((size_t)p*NN + n)*CC + c)*FF + f4*4);
        const int ks = f4 >> 1;
        uint* b = &XS[r*XST + ks*8 + (f4 & 1)];
        b[0] = f2tf32(v.x); b[2] = f2tf32(v.y);
        b[4] = f2tf32(v.z); b[6] = f2tf32(v.w);
    }
    for (int i = tid; i < 128*4; i += 256) {
        const int r = i >> 2, j = i & 3;
        XS[r*XST + 64 + 2*j + 1] = 0;
    }
    __syncthreads();

    const int warp = tid >> 5, lane = tid & 31;
    const int rowBase = (warp & 3) * 32;
    const int colBase = (warp >> 2) * 80;
    const int r  = lane >> 2;
    const int kk = lane & 3;

    float acc[2][10][4];
    #pragma unroll
    for (int mt = 0; mt < 2; ++mt)
        #pragma unroll
        for (int nt = 0; nt < 10; ++nt)
            #pragma unroll
            for (int q = 0; q < 4; ++q) acc[mt][nt][q] = 0.f;

    #pragma unroll 1
    for (int ks = 0; ks < 9; ++ks) {
        uint a[2][4];
        #pragma unroll
        for (int mt = 0; mt < 2; ++mt) {
            const int rb = rowBase + mt*16;
            const uint2 lo = *(const uint2*)&XS[(rb + r    )*XST + ks*8 + 2*kk];
            const uint2 hi = *(const uint2*)&XS[(rb + r + 8)*XST + ks*8 + 2*kk];
            a[mt][0] = lo.x; a[mt][1] = hi.x; a[mt][2] = lo.y; a[mt][3] = hi.y;
        }
        #pragma unroll
        for (int nt = 0; nt < 10; ++nt) {
            const uint2 b = *(const uint2*)&WS[(colBase + nt*8 + r)*WST + ks*8 + 2*kk];
            mma_tf32(acc[0][nt], a[0], b.x, b.y);
            mma_tf32(acc[1][nt], a[1], b.x, b.y);
        }
    }

    const size_t pnc = (size_t)p*NN;
    #pragma unroll
    for (int mt = 0; mt < 2; ++mt) {
        #pragma unroll
        for (int half = 0; half < 2; ++half) {
            const int n = n0 + rowBase + mt*16 + r + half*8;
            if (n >= NN) continue;
            const size_t base = (pnc + n)*CC + c;
            #pragma unroll
            for (int nt = 0; nt < 10; ++nt) {
                const int g = colBase + nt*8 + kk*2;
                float2 v;
                v.x = acc[mt][nt][half*2 + 0] + sbias[g];
                v.y = acc[mt][nt][half*2 + 1] + sbias[g+1];
                if (g < 16)      *(float2*)(g_A + base*FE + g)      = v;
                else if (g < 32) *(float2*)(g_B + base*FE + (g-16)) = v;
                else if (g < 96) *(float2*)(g_P + base*FN + (g-32)) = v;
                else             *(float2*)(g_Y + base*FN + (g-96)) = v;
            }
        }
    }
}

// ---------------------------------------------------------------------------
// gate: per edge, compute softmax class weights; write one 32B bucket record
// {src, w0..w4} into dst's slot list. No Y access, no wide atomics.
// ---------------------------------------------------------------------------
__global__ __launch_bounds__(256) void gate_kernel(
    const void* __restrict__ ei,
    const float* __restrict__ We2, const float* __restrict__ be2)
{
    __shared__ float sW2[CC*FE];
    __shared__ float sb2[CC];

    const int p = blockIdx.y;
    for (int i = threadIdx.x; i < CC*FE; i += blockDim.x)
        sW2[i] = We2[p*CC*FE + i];
    if (threadIdx.x < CC) sb2[threadIdx.x] = be2[p*CC + threadIdx.x];
    __syncthreads();

    const long long* q = (const long long*)ei;
    int ok = 1;
    #pragma unroll
    for (int i = 0; i < 16; ++i) {
        const long long v = q[i];
        ok &= (v >= 0) && (v < NN);
    }

    const long long* ei64 = (const long long*)ei;
    const int*       ei32 = (const int*)ei;
    const size_t base = (size_t)p*2*EE;

    const int e = blockIdx.x*blockDim.x + threadIdx.x;
    int s, d;
    if (ok) {
        s = (int)ei64[base + e];
        d = (int)ei64[base + EE + e];
    } else {
        s = ei32[base + e];
        d = ei32[base + EE + e];
    }

    const float4* Ad = (const float4*)(g_A + ((size_t)p*NN + d)*(CC*FE));
    const float4* Bs = (const float4*)(g_B + ((size_t)p*NN + s)*(CC*FE));

    float lg[CC];
    #pragma unroll
    for (int c = 0; c < CC; ++c) {
        float l = sb2[c];
        #pragma unroll
        for (int j = 0; j < 4; ++j) {
            const float4 a = Ad[c*4 + j];
            const float4 b = Bs[c*4 + j];
            l += tanh_fast(a.x + b.x) * sW2[c*FE + 4*j + 0]
               + tanh_fast(a.y + b.y) * sW2[c*FE + 4*j + 1]
               + tanh_fast(a.z + b.z) * sW2[c*FE + 4*j + 2]
               + tanh_fast(a.w + b.w) * sW2[c*FE + 4*j + 3];
        }
        lg[c] = l;
    }

    float mx = lg[0];
    #pragma unroll
    for (int c = 1; c < CC; ++c) mx = fmaxf(mx, lg[c]);
    float w[CC];
    float sum = 0.f;
    #pragma unroll
    for (int c = 0; c < CC; ++c) { w[c] = expf(lg[c] - mx); sum += w[c]; }
    const float inv = 1.f / sum;

    const int slot = atomicAdd(&g_deg[p*NN + d], 1);
    if (slot < SLOTS) {
        float* rec = g_bkt + ((size_t)(p*NN + d)*SLOTS + slot)*8;
        *(float4*)(rec)     = make_float4(__int_as_float(s),
                                          w[0]*inv, w[1]*inv, w[2]*inv);
        *(float4*)(rec + 4) = make_float4(w[3]*inv, w[4]*inv, 0.f, 0.f);
    }
}

// ---------------------------------------------------------------------------
// aggr: thread = (node, class, float4-chunk). acc = P; loop bucket records,
// gather Y[src] coalesced; h = tanh(acc) written as tf32 into g_H.
// ---------------------------------------------------------------------------
__global__ __launch_bounds__(256) void aggr_kernel()
{
    const int p = blockIdx.z;
    const int idx = blockIdx.x*256 + threadIdx.x;
    if (idx >= NN*80) return;
    const int n   = idx / 80;
    const int rem = idx % 80;
    const int c   = rem >> 4;
    const int qd  = rem & 15;

    const size_t pbase = (((size_t)p*NN + n)*CC + c)*FN + qd*4;
    float4 acc = *(const float4*)(g_P + pbase);

    const int deg = min(g_deg[p*NN + n], SLOTS);
    const float4* rec = (const float4*)(g_bkt + (size_t)(p*NN + n)*SLOTS*8);

    for (int i = 0; i < deg; ++i) {
        const float4 r0 = rec[2*i];
        const int src = __float_as_int(r0.x);
        float wv;
        if (c == 0)      wv = r0.y;
        else if (c == 1) wv = r0.z;
        else if (c == 2) wv = r0.w;
        else {
            const float4 r1 = rec[2*i + 1];
            wv = (c == 3) ? r1.x : r1.y;
        }
        const float4 y = *(const float4*)(g_Y + (((size_t)p*NN + src)*CC + c)*FN + qd*4);
        acc.x += wv*y.x; acc.y += wv*y.y; acc.z += wv*y.z; acc.w += wv*y.w;
    }

    uint4 t;
    t.x = f2tf32(tanh_fast(acc.x));
    t.y = f2tf32(tanh_fast(acc.y));
    t.z = f2tf32(tanh_fast(acc.z));
    t.w = f2tf32(tanh_fast(acc.w));
    *(uint4*)(g_H + pbase) = t;
}

// ---------------------------------------------------------------------------
// G2: out = tanh(H . W2^T + b2), H already tf32. 128 nodes/block.
// ---------------------------------------------------------------------------
#define HST 68
#define W2T 68

__global__ __launch_bounds__(256, 2) void g2_kernel(
    const float* __restrict__ bn2, float* __restrict__ out)
{
    extern __shared__ __align__(16) uint smem_u[];
    uint*  HS  = smem_u;
    uint*  W2S = HS + 128*HST;
    float* sb2 = (float*)(W2S + 64*W2T);

    const int c = blockIdx.y, p = blockIdx.z, tid = threadIdx.x;
    const int n0 = blockIdx.x * 128;
    const int pc = p*CC + c;

    const uint* w2 = g_W2t + (size_t)pc*64*64;
    for (int i = tid; i < 64*16; i += 256) {
        const int g = i >> 4, j = i & 15;
        *(uint4*)&W2S[g*W2T + j*4] = *(const uint4*)&w2[g*64 + j*4];
    }
    if (tid < FN) sb2[tid] = bn2[pc*FN + tid];

    for (int i = tid; i < 128*16; i += 256) {
        const int r = i >> 4, f4 = i & 15;
        const int n = n0 + r;
        uint4 t = make_uint4(0, 0, 0, 0);
        if (n < NN)
            t = *(const uint4*)(g_H + (((size_t)p*NN + n)*CC + c)*FN + f4*4);
        const int ks = f4 >> 1;
        uint* b = &HS[r*HST + ks*8 + (f4 & 1)];
        b[0] = t.x; b[2] = t.y; b[4] = t.z; b[6] = t.w;
    }
    __syncthreads();

    const int warp = tid >> 5, lane = tid & 31;
    const int rowBase = (warp & 3) * 32;
    const int colBase = (warp >> 2) * 32;
    const int r  = lane >> 2;
    const int kk = lane & 3;

    float acc[2][4][4];
    #pragma unroll
    for (int mt = 0; mt < 2; ++mt)
        #pragma unroll
        for (int nt = 0; nt < 4; ++nt)
            #pragma unroll
            for (int q = 0; q < 4; ++q) acc[mt][nt][q] = 0.f;

    #pragma unroll 1
    for (int ks = 0; ks < 8; ++ks) {
        uint a[2][4];
        #pragma unroll
        for (int mt = 0; mt < 2; ++mt) {
            const int rb = rowBase + mt*16;
            const uint2 lo = *(const uint2*)&HS[(rb + r    )*HST + ks*8 + 2*kk];
            const uint2 hi = *(const uint2*)&HS[(rb + r + 8)*HST + ks*8 + 2*kk];
            a[mt][0] = lo.x; a[mt][1] = hi.x; a[mt][2] = lo.y; a[mt][3] = hi.y;
        }
        #pragma unroll
        for (int nt = 0; nt < 4; ++nt) {
            const uint2 b = *(const uint2*)&W2S[(colBase + nt*8 + r)*W2T + ks*8 + 2*kk];
            mma_tf32(acc[0][nt], a[0], b.x, b.y);
            mma_tf32(acc[1][nt], a[1], b.x, b.y);
        }
    }

    #pragma unroll
    for (int mt = 0; mt < 2; ++mt) {
        #pragma unroll
        for (int half = 0; half < 2; ++half) {
            const int n = n0 + rowBase + mt*16 + r + half*8;
            if (n >= NN) continue;
            float* op = out + (((size_t)p*NN + n)*CC + c)*FN;
            #pragma unroll
            for (int nt = 0; nt < 4; ++nt) {
                const int g = colBase + nt*8 + kk*2;
                float2 v;
                v.x = tanhf(acc[mt][nt][half*2 + 0] + sb2[g]);
                v.y = tanhf(acc[mt][nt][half*2 + 1] + sb2[g+1]);
                *(float2*)(op + g) = v;
            }
        }
    }
}

extern "C" void kernel_launch(void* const* d_in, const int* in_sizes, int n_in,
                              void* d_out, int out_size) {
    const float* x   = (const float*)d_in[0];
    const void*  ei  = d_in[1];
    const float* We1 = (const float*)d_in[2];
    const float* be1 = (const float*)d_in[3];
    const float* We2 = (const float*)d_in[4];
    const float* be2 = (const float*)d_in[5];
    const float* Wn1 = (const float*)d_in[6];
    const float* bn1 = (const float*)d_in[7];
    const float* Wn2 = (const float*)d_in[8];
    const float* bn2 = (const float*)d_in[9];
    float* out = (float*)d_out;

    const int smem1 = (128*XST + 160*WST)*4 + 160*4;   // 88192 B
    const int smem2 = (128*HST + 64*W2T)*4 + 64*4;     // 52480 B
    cudaFuncSetAttribute(g1_kernel,
                         cudaFuncAttributeMaxDynamicSharedMemorySize, smem1);
    cudaFuncSetAttribute(g2_kernel,
                         cudaFuncAttributeMaxDynamicSharedMemorySize, smem2);

    wprep_kernel<<<PP*CC, 256>>>(We1, Wn1, Wn2);
    zero_deg_kernel<<<(PP*NN + 255)/256, 256>>>();

    dim3 gg((NN + 127)/128, CC, PP);
    g1_kernel<<<gg, 256, smem1>>>(x, be1, bn1);

    dim3 ge(EE/256, PP);
    gate_kernel<<<ge, 256>>>(ei, We2, be2);

    dim3 ga((NN*80 + 255)/256, 1, PP);
    aggr_kernel<<<ga, 256>>>();

    g2_kernel<<<gg, 256, smem2>>>(bn2, out);
}